// round 1
// baseline (speedup 1.0000x reference)
#include <cuda_runtime.h>

// Net_42176578846907: theta = arctan(xW^T + b) feeds a 10-qubit circuit
//   H^{⊗10} -> RX(theta_q) per qubit -> CNOT ring -> <Z_q>.
// Analytically: H layer gives uniform superposition |+>^{⊗10}; |+> is an
// RX eigenstate (global phase e^{-i t/2}); the uniform state is invariant
// under the CNOT permutations; hence <Z_q> = 0 for all q, all samples.
// In the reference's fp32 arithmetic the amplitudes stay BIT-identical at
// every step (identical op sequences per amplitude), so the two halves of
// each <Z> reduction are bit-equal and the output is exactly 0.0f.
// Fastest correct kernel: write 32768*10 zeros.

__global__ void zero_output_kernel(float4* __restrict__ out4, int n4,
                                   float* __restrict__ out_tail, int tail_base, int n) {
    int i = blockIdx.x * blockDim.x + threadIdx.x;
    if (i < n4) {
        out4[i] = make_float4(0.0f, 0.0f, 0.0f, 0.0f);
    }
    // tail (out_size not multiple of 4): first few threads mop up
    int t = tail_base + i;
    if (i < 4 && t < n) {
        out_tail[t] = 0.0f;
    }
}

extern "C" void kernel_launch(void* const* d_in, const int* in_sizes, int n_in,
                              void* d_out, int out_size) {
    (void)d_in; (void)in_sizes; (void)n_in;
    int n  = out_size;        // 327680 floats expected
    int n4 = n >> 2;          // float4 count
    int tail_base = n4 << 2;

    const int threads = 256;
    int blocks = (n4 + threads - 1) / threads;
    if (blocks < 1) blocks = 1;

    zero_output_kernel<<<blocks, threads>>>(
        (float4*)d_out, n4, (float*)d_out, tail_base, n);
}